// round 5
// baseline (speedup 1.0000x reference)
#include <cuda_runtime.h>
#include <math.h>

// P2V: out[b,vox] = top2-margin of softmax_n( |s2| * exp(-|s1| * |xyz[b,:,n]-grid[:,vox]|^2) )
// margin = (exp(v0)-exp(v1)) / sum_n exp(v_n),  v_n in (0,1]
//
// v_n = 2^( kx0*g0 + kx1*g1 + kx2*g2 + p_n + lw_vox )   (one MUFU ex2 per n)
//   kxc = 2*s1*log2e*x_c,  p_n = -s1*log2e*|x_n|^2      (split pair-packed tables T01/T23)
//   lw  = log2|s2| - s1*log2e*|g|^2                     (per-voxel table {g0,g1,g2,lw})
// exp(v) for softmax sum: deg-4 minimax poly P(v)=Q(v)*v+c0 on [0,1], S=fma2(Q,v,S),
// +1024*c0 added once. Top-2 tracked on the EXPONENT acc (monotone) with scalar FMNMX,
// overlapping the MUFU ex2; exact exp2f/expf applied only to the final two values.

typedef unsigned long long u64;

#define VOXN 32768
#define NN   1024

// T01[b][pair] = {kx0_n, kx0_n1, kx1_n, kx1_n1};  T23[b][pair] = {kx2_n, kx2_n1, p_n, p_n1}
__device__ __align__(256) float4 T01[4][512];
__device__ __align__(256) float4 T23[4][512];
__device__ __align__(16)  float4 g_vox[VOXN];

__device__ __forceinline__ u64 pk2(float lo, float hi) {
    u64 r; asm("mov.b64 %0, {%1, %2};" : "=l"(r) : "f"(lo), "f"(hi)); return r;
}
__device__ __forceinline__ void upk2(u64 v, float& lo, float& hi) {
    asm("mov.b64 {%0, %1}, %2;" : "=f"(lo), "=f"(hi) : "l"(v));
}
__device__ __forceinline__ u64 fma2(u64 a, u64 b, u64 c) {
    u64 d; asm("fma.rn.f32x2 %0, %1, %2, %3;" : "=l"(d) : "l"(a), "l"(b), "l"(c)); return d;
}
__device__ __forceinline__ u64 add2(u64 a, u64 b) {
    u64 d; asm("add.rn.f32x2 %0, %1, %2;" : "=l"(d) : "l"(a), "l"(b)); return d;
}
__device__ __forceinline__ float ex2f(float x) {
    float r; asm("ex2.approx.ftz.f32 %0, %1;" : "=f"(r) : "f"(x)); return r;
}

// deg-4 minimax for e^x on [0,1]: ((((c4 x + c3)x + c2)x + c1)x + c0, |err| ~ 3e-5
#define C4F 0.0695600f
#define C3F 0.1400096f
#define C2F 0.5099252f
#define C1F 0.9987378f
#define C0F 1.0000236f

// ---- fused prologue: blocks 0-127 per-voxel, blocks 128-143 per-(b,n) tables ----
__global__ void pv_prep(const float* __restrict__ xyz,
                        const float* __restrict__ grid,
                        const float* __restrict__ s1,
                        const float* __restrict__ s2) {
    const float L = 1.4426950408889634f;
    float s1a = fabsf(s1[0]);
    if (blockIdx.x < 128) {
        int vx = blockIdx.x * 256 + threadIdx.x;
        float g0 = grid[vx];
        float g1 = grid[VOXN + vx];
        float g2 = grid[2 * VOXN + vx];
        float lw = __log2f(fabsf(s2[0])) - s1a * L * (g0 * g0 + g1 * g1 + g2 * g2);
        g_vox[vx] = make_float4(g0, g1, g2, lw);
    } else {
        int i = (blockIdx.x - 128) * 256 + threadIdx.x;   // 0..4095
        if (i >= 4 * NN) return;
        int b = i >> 10, n = i & (NN - 1);
        float k = 2.0f * s1a * L;
        float x0 = xyz[b * 3 * NN + 0 * NN + n];
        float x1 = xyz[b * 3 * NN + 1 * NN + n];
        float x2 = xyz[b * 3 * NN + 2 * NN + n];
        int pr = n >> 1, h = n & 1;
        float* t01 = reinterpret_cast<float*>(&T01[b][pr]);
        float* t23 = reinterpret_cast<float*>(&T23[b][pr]);
        t01[0 + h] = k * x0;
        t01[2 + h] = k * x1;
        t23[0 + h] = k * x2;
        t23[2 + h] = -s1a * L * (x0 * x0 + x1 * x1 + x2 * x2);
    }
}

// ---- main: one warp -> 4 voxels x 1 batch = 4 outputs --------------------
// block = 4 warps, same batch, 16 consecutive voxels (shared table rows -> L1 broadcast)
__global__ void __launch_bounds__(128, 7) pv_main(float* __restrict__ out)
{
    int lane = threadIdx.x & 31;
    int wig  = threadIdx.x >> 5;         // warp in block
    int b    = blockIdx.x & 3;
    int vsg  = blockIdx.x >> 2;          // 0..2047
    int vox0 = vsg * 16 + wig * 4;

    // per-voxel broadcast constants
    u64 G[4][3], LW[4];
    #pragma unroll
    for (int v = 0; v < 4; v++) {
        float4 gv = g_vox[vox0 + v];
        G[v][0] = pk2(gv.x, gv.x);
        G[v][1] = pk2(gv.y, gv.y);
        G[v][2] = pk2(gv.z, gv.z);
        LW[v]   = pk2(gv.w, gv.w);
    }

    const u64 Cq3 = pk2(C4F, C4F);
    const u64 Cq2 = pk2(C3F, C3F);
    const u64 Cq1 = pk2(C2F, C2F);
    const u64 Cq0 = pk2(C1F, C1F);

    u64 S[4];
    float m0[4], m1[4];
    #pragma unroll
    for (int v = 0; v < 4; v++) { S[v] = 0ull; m0[v] = -1e30f; m1[v] = -1e30f; }

    const ulonglong2* p01 = reinterpret_cast<const ulonglong2*>(&T01[b][lane]);
    const ulonglong2* p23 = reinterpret_cast<const ulonglong2*>(&T23[b][lane]);

    #pragma unroll 1
    for (int j = 0; j < 16; j++) {
        ulonglong2 x01 = p01[j * 32];   // {kx0 pair, kx1 pair}  (lane-stride 16B, coalesced)
        ulonglong2 x23 = p23[j * 32];   // {kx2 pair, p   pair}

        #pragma unroll
        for (int v = 0; v < 4; v++) {
            u64 acc = fma2(x01.x, G[v][0], add2(x23.y, LW[v]));
            acc = fma2(x01.y, G[v][1], acc);
            acc = fma2(x23.x, G[v][2], acc);
            float alo, ahi; upk2(acc, alo, ahi);
            // top-2 on exponent (ALU pipe, overlaps MUFU below)
            m1[v] = fmaxf(m1[v], fminf(m0[v], alo));
            m0[v] = fmaxf(m0[v], alo);
            m1[v] = fmaxf(m1[v], fminf(m0[v], ahi));
            m0[v] = fmaxf(m0[v], ahi);
            u64 vv = pk2(ex2f(alo), ex2f(ahi));      // v in [0,1]
            u64 q = fma2(Cq3, vv, Cq2);
            q = fma2(q, vv, Cq1);
            q = fma2(q, vv, Cq0);
            S[v] = fma2(q, vv, S[v]);
        }
    }

    // cross-lane reduction per output (butterfly top-2 on exponents + sum)
    float res = 0.f;
    #pragma unroll
    for (int v = 0; v < 4; v++) {
        float slo, shi; upk2(S[v], slo, shi);
        float Sf = slo + shi;
        float M0 = m0[v], M1 = m1[v];
        #pragma unroll
        for (int off = 16; off; off >>= 1) {
            float o0 = __shfl_xor_sync(0xffffffffu, M0, off);
            float o1 = __shfl_xor_sync(0xffffffffu, M1, off);
            float os = __shfl_xor_sync(0xffffffffu, Sf, off);
            M1 = fmaxf(fmaxf(M1, o1), fminf(M0, o0));
            M0 = fmaxf(M0, o0);
            Sf += os;
        }
        if (lane == v) {
            float v0 = exp2f(M0), v1 = exp2f(M1);
            res = (__expf(v0) - __expf(v1)) / (Sf + 1024.0f * C0F);
        }
    }
    if (lane < 4)
        out[b * VOXN + vox0 + lane] = res;
}

extern "C" void kernel_launch(void* const* d_in, const int* in_sizes, int n_in,
                              void* d_out, int out_size) {
    const float* xyz = nullptr; const float* grid = nullptr;
    const float* s1 = nullptr;  const float* s2 = nullptr;
    for (int i = 0; i < n_in; i++) {
        if (in_sizes[i] == 4 * 3 * NN)      xyz = (const float*)d_in[i];
        else if (in_sizes[i] == 3 * VOXN)   grid = (const float*)d_in[i];
        else if (in_sizes[i] == 1) { if (!s1) s1 = (const float*)d_in[i]; else s2 = (const float*)d_in[i]; }
    }
    float* out = (float*)d_out;

    pv_prep<<<144, 256>>>(xyz, grid, s1, s2);
    // 131072 outputs, 4 per warp -> 32768 warps -> 8192 blocks of 4 warps
    pv_main<<<8192, 128>>>(out);
}

// round 6
// speedup vs baseline: 1.0207x; 1.0207x over previous
#include <cuda_runtime.h>
#include <math.h>

// P2V: out[b,vox] = top2-margin of softmax_n( |s2| * exp(-|s1| * |xyz[b,:,n]-grid[:,vox]|^2) )
// margin = (exp(v0)-exp(v1)) / sum_n exp(v_n),  v_n in (0,1]
//
// v_n = 2^( kx0*g0 + kx1*g1 + kx2*g2 + p_n + lw_vox )   (one MUFU ex2 per n)
// Split pair-packed tables, single fused array for immediate-offset loads:
//   TAB[0][b][pair] = {kx0_n,kx0_n1, kx1_n,kx1_n1}
//   TAB[1][b][pair] = {kx2_n,kx2_n1, p_n,  p_n1 }
// Sum of exp(v): deg-4 minimax poly P(v)=Q(v)*v+c0 on [0,1], S=fma2(Q,v,S), +1024*c0 once.
// Top-2 tracked on the exponent acc (monotone) via scalar FMNMX (ALU pipe, parallel to MUFU).

typedef unsigned long long u64;

#define VOXN 32768
#define NN   1024

__device__ __align__(256) float4 TAB[2][4][512];   // [half][batch][pair], 16B rows
__device__ __align__(16)  float4 g_vox[VOXN];

__device__ __forceinline__ u64 pk2(float lo, float hi) {
    u64 r; asm("mov.b64 %0, {%1, %2};" : "=l"(r) : "f"(lo), "f"(hi)); return r;
}
__device__ __forceinline__ void upk2(u64 v, float& lo, float& hi) {
    asm("mov.b64 {%0, %1}, %2;" : "=f"(lo), "=f"(hi) : "l"(v));
}
__device__ __forceinline__ u64 fma2(u64 a, u64 b, u64 c) {
    u64 d; asm("fma.rn.f32x2 %0, %1, %2, %3;" : "=l"(d) : "l"(a), "l"(b), "l"(c)); return d;
}
__device__ __forceinline__ u64 add2(u64 a, u64 b) {
    u64 d; asm("add.rn.f32x2 %0, %1, %2;" : "=l"(d) : "l"(a), "l"(b)); return d;
}
__device__ __forceinline__ float ex2f(float x) {
    float r; asm("ex2.approx.ftz.f32 %0, %1;" : "=f"(r) : "f"(x)); return r;
}

// deg-4 minimax for e^x on [0,1], |err| ~ 3e-5
#define C4F 0.0695600f
#define C3F 0.1400096f
#define C2F 0.5099252f
#define C1F 0.9987378f
#define C0F 1.0000236f

// ---- fused prologue: blocks 0-127 per-voxel, blocks 128-143 per-(b,n) tables ----
__global__ void pv_prep(const float* __restrict__ xyz,
                        const float* __restrict__ grid,
                        const float* __restrict__ s1,
                        const float* __restrict__ s2) {
    const float L = 1.4426950408889634f;
    float s1a = fabsf(s1[0]);
    if (blockIdx.x < 128) {
        int vx = blockIdx.x * 256 + threadIdx.x;
        float g0 = grid[vx];
        float g1 = grid[VOXN + vx];
        float g2 = grid[2 * VOXN + vx];
        float lw = __log2f(fabsf(s2[0])) - s1a * L * (g0 * g0 + g1 * g1 + g2 * g2);
        g_vox[vx] = make_float4(g0, g1, g2, lw);
    } else {
        int i = (blockIdx.x - 128) * 256 + threadIdx.x;   // 0..4095
        if (i >= 4 * NN) return;
        int b = i >> 10, n = i & (NN - 1);
        float k = 2.0f * s1a * L;
        float x0 = xyz[b * 3 * NN + 0 * NN + n];
        float x1 = xyz[b * 3 * NN + 1 * NN + n];
        float x2 = xyz[b * 3 * NN + 2 * NN + n];
        int pr = n >> 1, h = n & 1;
        float* t01 = reinterpret_cast<float*>(&TAB[0][b][pr]);
        float* t23 = reinterpret_cast<float*>(&TAB[1][b][pr]);
        t01[0 + h] = k * x0;
        t01[2 + h] = k * x1;
        t23[0 + h] = k * x2;
        t23[2 + h] = -s1a * L * (x0 * x0 + x1 * x1 + x2 * x2);
    }
}

// ---- main: one warp -> 4 voxels x 2 batches = 8 outputs --------------------
// block = 4 warps, same batch-pair, 16 consecutive voxels.
__global__ void __launch_bounds__(128, 6) pv_main(float* __restrict__ out)
{
    int lane = threadIdx.x & 31;
    int wig  = threadIdx.x >> 5;
    int bh   = blockIdx.x & 1;           // batches {2bh, 2bh+1}
    int vsg  = blockIdx.x >> 1;          // 0..2047
    int vox0 = vsg * 16 + wig * 4;

    // per-voxel broadcast constants
    u64 G[4][3], LW[4];
    #pragma unroll
    for (int v = 0; v < 4; v++) {
        float4 gv = g_vox[vox0 + v];
        G[v][0] = pk2(gv.x, gv.x);
        G[v][1] = pk2(gv.y, gv.y);
        G[v][2] = pk2(gv.z, gv.z);
        LW[v]   = pk2(gv.w, gv.w);
    }

    const u64 Cq3 = pk2(C4F, C4F);
    const u64 Cq2 = pk2(C3F, C3F);
    const u64 Cq1 = pk2(C2F, C2F);
    const u64 Cq0 = pk2(C1F, C1F);

    u64 S[8];
    float m0[8], m1[8];
    #pragma unroll
    for (int o = 0; o < 8; o++) { S[o] = 0ull; m0[o] = -1e30f; m1[o] = -1e30f; }

    // single base pointer; the 4 loads per iteration are immediate offsets off it
    const char* base = reinterpret_cast<const char*>(&TAB[0][2 * bh][lane]);
    const int OFF23 = 4 * 512 * 16;          // TAB[1] - TAB[0]
    const int OFFB  = 512 * 16;              // batch+1 within a half

    #pragma unroll 2
    for (int j = 0; j < 16; j++) {
        ulonglong2 a01 = *reinterpret_cast<const ulonglong2*>(base);
        ulonglong2 a23 = *reinterpret_cast<const ulonglong2*>(base + OFF23);
        ulonglong2 b01 = *reinterpret_cast<const ulonglong2*>(base + OFFB);
        ulonglong2 b23 = *reinterpret_cast<const ulonglong2*>(base + OFF23 + OFFB);
        base += 512;

        #pragma unroll
        for (int v = 0; v < 4; v++) {
            #pragma unroll
            for (int bi = 0; bi < 2; bi++) {
                const ulonglong2& x01 = bi ? b01 : a01;
                const ulonglong2& x23 = bi ? b23 : a23;
                int o = v * 2 + bi;
                u64 acc = fma2(x01.x, G[v][0], add2(x23.y, LW[v]));
                acc = fma2(x01.y, G[v][1], acc);
                acc = fma2(x23.x, G[v][2], acc);
                float alo, ahi; upk2(acc, alo, ahi);
                // top-2 on exponent (ALU pipe, overlaps MUFU below)
                m1[o] = fmaxf(m1[o], fminf(m0[o], alo));
                m0[o] = fmaxf(m0[o], alo);
                m1[o] = fmaxf(m1[o], fminf(m0[o], ahi));
                m0[o] = fmaxf(m0[o], ahi);
                u64 vv = pk2(ex2f(alo), ex2f(ahi));      // v in [0,1]
                u64 q = fma2(Cq3, vv, Cq2);
                q = fma2(q, vv, Cq1);
                q = fma2(q, vv, Cq0);
                S[o] = fma2(q, vv, S[o]);
            }
        }
    }

    // cross-lane reduction per output (butterfly top-2 on exponents + sum)
    float res = 0.f;
    #pragma unroll
    for (int o = 0; o < 8; o++) {
        float slo, shi; upk2(S[o], slo, shi);
        float Sf = slo + shi;
        float M0 = m0[o], M1 = m1[o];
        #pragma unroll
        for (int off = 16; off; off >>= 1) {
            float o0 = __shfl_xor_sync(0xffffffffu, M0, off);
            float o1 = __shfl_xor_sync(0xffffffffu, M1, off);
            float os = __shfl_xor_sync(0xffffffffu, Sf, off);
            M1 = fmaxf(fmaxf(M1, o1), fminf(M0, o0));
            M0 = fmaxf(M0, o0);
            Sf += os;
        }
        if (lane == o) {
            float v0 = exp2f(M0), v1 = exp2f(M1);
            res = (__expf(v0) - __expf(v1)) / (Sf + 1024.0f * C0F);
        }
    }
    if (lane < 8) {
        int v = lane >> 1, bi = lane & 1;
        out[(2 * bh + bi) * VOXN + vox0 + v] = res;
    }
}

extern "C" void kernel_launch(void* const* d_in, const int* in_sizes, int n_in,
                              void* d_out, int out_size) {
    const float* xyz = nullptr; const float* grid = nullptr;
    const float* s1 = nullptr;  const float* s2 = nullptr;
    for (int i = 0; i < n_in; i++) {
        if (in_sizes[i] == 4 * 3 * NN)      xyz = (const float*)d_in[i];
        else if (in_sizes[i] == 3 * VOXN)   grid = (const float*)d_in[i];
        else if (in_sizes[i] == 1) { if (!s1) s1 = (const float*)d_in[i]; else s2 = (const float*)d_in[i]; }
    }
    float* out = (float*)d_out;

    pv_prep<<<144, 256>>>(xyz, grid, s1, s2);
    // 131072 outputs, 8 per warp -> 16384 warps -> 4096 blocks of 4 warps
    pv_main<<<4096, 128>>>(out);
}